// round 7
// baseline (speedup 1.0000x reference)
#include <cuda_runtime.h>
#include <cuda_bf16.h>
#include <math.h>
#include <stdint.h>

// ---------------- problem constants ----------------
#define BATCH   16
#define SEQ     768
#define MTOK    (BATCH*SEQ)       // 12288
#define DMODEL  512
#define DSTATE  128
#define DCONV   4
#define DINNER  1024
#define HEADDIM 64
#define NHEADS  16
#define CONVDIM (DINNER + 2*DSTATE)            // 1280
#define DINPROJ (2*DINNER + 2*DSTATE + NHEADS) // 2320
#define NINPAD  2432                            // 19*128
#define NLAYER  28
#define VOCAB   256
#define EPSF    1e-5f

// ---------------- device scratch ----------------
__device__ float g_hidden[MTOK*DMODEL];
__device__ float g_resid [MTOK*DMODEL];
__device__ float g_zx    [(size_t)MTOK*DINPROJ];
__device__ float g_xbc   [(size_t)MTOK*CONVDIM];
__device__ float g_dt    [MTOK*NHEADS];
__device__ float g_y     [(size_t)MTOK*DINNER];
__device__ float g_logits[(size_t)MTOK*VOCAB];
__device__ float g_loss_sum;

__device__ __nv_bfloat16 g_nh[MTOK*DMODEL],  g_nl[MTOK*DMODEL];
__device__ __nv_bfloat16 g_gh[MTOK*DINNER],  g_gl[MTOK*DINNER];
__device__ __nv_bfloat16 g_wih[(size_t)NLAYER*NINPAD*DMODEL], g_wil[(size_t)NLAYER*NINPAD*DMODEL];
__device__ __nv_bfloat16 g_woh[(size_t)NLAYER*DMODEL*DINNER], g_wol[(size_t)NLAYER*DMODEL*DINNER];
__device__ __nv_bfloat16 g_eh[VOCAB*DMODEL], g_el[VOCAB*DMODEL];

// ---------------- PTX helpers (family-safe) ----------------
__device__ __forceinline__ uint32_t smem_u32(const void* p) {
    uint32_t a;
    asm("{ .reg .u64 t; cvta.to.shared.u64 t, %1; cvt.u32.u64 %0, t; }" : "=r"(a) : "l"(p));
    return a;
}
__device__ __forceinline__ void cp16(uint32_t dst, const void* src) {
    asm volatile("cp.async.cg.shared.global [%0], [%1], 16;" :: "r"(dst), "l"(src));
}
__device__ __forceinline__ void ldm_x4(uint32_t addr, uint32_t& r0, uint32_t& r1, uint32_t& r2, uint32_t& r3) {
    asm volatile("ldmatrix.sync.aligned.m8n8.x4.shared.b16 {%0,%1,%2,%3}, [%4];"
                 : "=r"(r0), "=r"(r1), "=r"(r2), "=r"(r3) : "r"(addr));
}
__device__ __forceinline__ void mma_bf16(float* c, const uint32_t* a, const uint32_t* b) {
    asm volatile(
        "mma.sync.aligned.m16n8k16.row.col.f32.bf16.bf16.f32 "
        "{%0,%1,%2,%3}, {%4,%5,%6,%7}, {%8,%9}, {%0,%1,%2,%3};"
        : "+f"(c[0]), "+f"(c[1]), "+f"(c[2]), "+f"(c[3])
        : "r"(a[0]), "r"(a[1]), "r"(a[2]), "r"(a[3]), "r"(b[0]), "r"(b[1]));
}
typedef unsigned long long u64t;
__device__ __forceinline__ u64t pack2(float x, float y) {
    u64t r; asm("mov.b64 %0, {%1, %2};" : "=l"(r) : "f"(x), "f"(y)); return r;
}
__device__ __forceinline__ u64t mul2(u64t a, u64t b) {
    u64t d; asm("mul.rn.f32x2 %0, %1, %2;" : "=l"(d) : "l"(a), "l"(b)); return d;
}
__device__ __forceinline__ u64t fma2(u64t a, u64t b, u64t c) {
    u64t d; asm("fma.rn.f32x2 %0, %1, %2, %3;" : "=l"(d) : "l"(a), "l"(b), "l"(c)); return d;
}
__device__ __forceinline__ void unpack2(u64t v, float& x, float& y) {
    asm("mov.b64 {%0, %1}, %2;" : "=f"(x), "=f"(y) : "l"(v));
}

// ---------------- bf16x3 GEMM via mma.sync, 4-stage multistage ----------------
// C[M,N] = A[M,K]*B[N,K]^T, fp32 C. A,B as bf16 hi/lo pairs.
// 128x128 tile, KC=16, 4-stage cp.async ring, ONE barrier per chunk,
// fill issued before compute (prefetch distance 3). 256 threads, 2 CTAs/SM.
// smem row: 16 bf16 = 32B data + 16B pad = 48B stride (conflict-free ldmatrix).
#define ROWB   48
#define SUBT   (128*ROWB)      // 6144 per subtile
#define STAGEB (4*SUBT)        // 24576: Ah, Al, Bh, Bl
#define NSTG   4
#define GSMEM  (NSTG*STAGEB)   // 98304

__device__ __forceinline__ void fill_stage(uint32_t st,
        const __nv_bfloat16* __restrict__ Ah, const __nv_bfloat16* __restrict__ Al,
        const __nv_bfloat16* __restrict__ Bh, const __nv_bfloat16* __restrict__ Bl,
        int bm, int bn, int K, int kc, int tid)
{
    const size_t k0 = (size_t)kc * 16;
    const int row = tid >> 1;          // 0..127
    const int ch  = tid & 1;           // 16B chunk (2 per 32B row)
    const uint32_t soff = (uint32_t)row * ROWB + (uint32_t)ch * 16;
    const size_t goff = (size_t)row * K + (size_t)ch * 8;
    cp16(st + 0 * SUBT + soff, Ah + (size_t)bm * K + k0 + goff);
    cp16(st + 1 * SUBT + soff, Al + (size_t)bm * K + k0 + goff);
    cp16(st + 2 * SUBT + soff, Bh + (size_t)bn * K + k0 + goff);
    cp16(st + 3 * SUBT + soff, Bl + (size_t)bn * K + k0 + goff);
    asm volatile("cp.async.commit_group;" ::: "memory");
}

__global__ void __launch_bounds__(256, 2) gemm_bf16x3(
    const __nv_bfloat16* __restrict__ Ah, const __nv_bfloat16* __restrict__ Al,
    const __nv_bfloat16* __restrict__ Bh, const __nv_bfloat16* __restrict__ Bl,
    float* __restrict__ C, int M, int N, int K)
{
    extern __shared__ char smem[];
    const uint32_t sb = smem_u32(smem);
    const int tid  = threadIdx.x;
    const int wid  = tid >> 5, lane = tid & 31;
    const int wm   = wid >> 2, wn = wid & 3;
    const int bm   = blockIdx.y * 128, bn = blockIdx.x * 128;

    float acc[4][4][4];
    #pragma unroll
    for (int i = 0; i < 4; i++)
        #pragma unroll
        for (int j = 0; j < 4; j++)
            #pragma unroll
            for (int q = 0; q < 4; q++) acc[i][j][q] = 0.f;

    const int nc = K >> 4;   // K / 16

    // prologue: fill stages 0..2
    fill_stage(sb + 0 * STAGEB, Ah, Al, Bh, Bl, bm, bn, K, 0, tid);
    fill_stage(sb + 1 * STAGEB, Ah, Al, Bh, Bl, bm, bn, K, 1, tid);
    fill_stage(sb + 2 * STAGEB, Ah, Al, Bh, Bl, bm, bn, K, 2, tid);

    const int a_r = lane & 15;
    const int a_k = lane >> 4;
    const int b_r = ((lane >> 4) << 3) + (lane & 7);
    const int b_k = (lane >> 3) & 1;

    for (int c = 0; c < nc; ++c) {
        // ensure fill(c) complete: outstanding groups are {c .. min(c+2, nc-1)}
        const int rem = nc - 1 - c;
        if (rem >= 2)      asm volatile("cp.async.wait_group 2;" ::: "memory");
        else if (rem == 1) asm volatile("cp.async.wait_group 1;" ::: "memory");
        else               asm volatile("cp.async.wait_group 0;" ::: "memory");
        __syncthreads();   // the ONE barrier per chunk: also protects stage (c-1)%4 reuse

        if (c + 3 < nc)
            fill_stage(sb + (uint32_t)((c + 3) & 3) * STAGEB, Ah, Al, Bh, Bl, bm, bn, K, c + 3, tid);

        const uint32_t st = sb + (uint32_t)(c & 3) * STAGEB;
        const uint32_t a_base = st + (uint32_t)(wm * 64 + a_r) * ROWB + a_k * 16;
        const uint32_t b_base = st + 2 * SUBT + (uint32_t)(wn * 32 + b_r) * ROWB + b_k * 16;

        uint32_t bh[4][2], bl[4][2];
        #pragma unroll
        for (int bi = 0; bi < 2; ++bi) {
            uint32_t addr = b_base + (uint32_t)(bi * 16) * ROWB;
            ldm_x4(addr,        bh[2*bi][0], bh[2*bi][1], bh[2*bi+1][0], bh[2*bi+1][1]);
            ldm_x4(addr + SUBT, bl[2*bi][0], bl[2*bi][1], bl[2*bi+1][0], bl[2*bi+1][1]);
        }
        #pragma unroll
        for (int mi = 0; mi < 4; ++mi) {
            uint32_t ah[4], al[4];
            uint32_t addr = a_base + (uint32_t)(mi * 16) * ROWB;
            ldm_x4(addr,        ah[0], ah[1], ah[2], ah[3]);
            ldm_x4(addr + SUBT, al[0], al[1], al[2], al[3]);
            #pragma unroll
            for (int ni = 0; ni < 4; ++ni) mma_bf16(acc[mi][ni], ah, bh[ni]);
            #pragma unroll
            for (int ni = 0; ni < 4; ++ni) mma_bf16(acc[mi][ni], ah, bl[ni]);
            #pragma unroll
            for (int ni = 0; ni < 4; ++ni) mma_bf16(acc[mi][ni], al, bh[ni]);
        }
    }

    const int r  = lane >> 2;
    const int cc = (lane & 3) << 1;
    #pragma unroll
    for (int mi = 0; mi < 4; ++mi) {
        int m0 = bm + wm * 64 + mi * 16 + r;
        #pragma unroll
        for (int ni = 0; ni < 4; ++ni) {
            int n0 = bn + wn * 32 + ni * 8 + cc;
            if (n0 < N) {
                *reinterpret_cast<float2*>(C + (size_t)m0 * N + n0) =
                    make_float2(acc[mi][ni][0], acc[mi][ni][1]);
                *reinterpret_cast<float2*>(C + (size_t)(m0 + 8) * N + n0) =
                    make_float2(acc[mi][ni][2], acc[mi][ni][3]);
            }
        }
    }
}

// ---------------- generic helpers ----------------
__device__ __forceinline__ float blockReduceSum(float v) {
    __shared__ float sh[32];
    int lane = threadIdx.x & 31, wid = threadIdx.x >> 5;
    #pragma unroll
    for (int o = 16; o > 0; o >>= 1) v += __shfl_xor_sync(0xffffffffu, v, o);
    if (lane == 0) sh[wid] = v;
    __syncthreads();
    if (threadIdx.x == 0) {
        float t = 0.f;
        int nw = (blockDim.x + 31) >> 5;
        for (int i = 0; i < nw; i++) t += sh[i];
        sh[0] = t;
    }
    __syncthreads();
    return sh[0];
}
__device__ __forceinline__ float siluf(float x) { return x / (1.0f + expf(-x)); }

__device__ __forceinline__ void bf16split(float v, __nv_bfloat16* h, __nv_bfloat16* l) {
    __nv_bfloat16 hb = __float2bfloat16(v);
    *h = hb;
    *l = __float2bfloat16(v - __bfloat162float(hb));
}

// ---------------- weight split (with row padding) ----------------
__global__ void split_pad_kernel(const float* __restrict__ src, __nv_bfloat16* __restrict__ h,
                                 __nv_bfloat16* __restrict__ l, int nt, int np, int K, long total) {
    long idx = (long)blockIdx.x * blockDim.x + threadIdx.x;
    if (idx >= total) return;
    int k = (int)(idx % K);
    long t = idx / K;
    int r  = (int)(t % np);
    int ly = (int)(t / np);
    float v = (r < nt) ? src[((size_t)ly * nt + r) * K + k] : 0.0f;
    __nv_bfloat16 hh, ll;
    bf16split(v, &hh, &ll);
    h[idx] = hh; l[idx] = ll;
}

// ---------------- embedding + residual init ----------------
__global__ void embed_kernel(const int* __restrict__ tokens, const float* __restrict__ emb,
                             float* __restrict__ hid, float* __restrict__ res) {
    int idx = blockIdx.x * blockDim.x + threadIdx.x;
    if (idx >= MTOK * DMODEL) return;
    int m = idx >> 9;
    int d = idx & 511;
    hid[idx] = emb[tokens[m] * DMODEL + d];
    res[idx] = 0.0f;
}

// res += h ; out = rms(res)*w -> bf16 hi/lo
__global__ void add_rms_kernel(const float* __restrict__ h, float* __restrict__ res,
                               const float* __restrict__ w,
                               __nv_bfloat16* __restrict__ oh, __nv_bfloat16* __restrict__ ol) {
    int m = blockIdx.x;
    const float* hr = h + (size_t)m * DMODEL;
    float* rr = res + (size_t)m * DMODEL;
    float v[4]; float ss = 0.f;
    #pragma unroll
    for (int j = 0; j < 4; j++) {
        int d = threadIdx.x + j * 128;
        float x = hr[d] + rr[d];
        rr[d] = x;
        v[j] = x;
        ss += x * x;
    }
    float tot = blockReduceSum(ss);
    float scale = rsqrtf(tot * (1.0f / DMODEL) + EPSF);
    #pragma unroll
    for (int j = 0; j < 4; j++) {
        int d = threadIdx.x + j * 128;
        float o = v[j] * scale * w[d];
        __nv_bfloat16 hh, ll;
        bf16split(o, &hh, &ll);
        oh[(size_t)m * DMODEL + d] = hh;
        ol[(size_t)m * DMODEL + d] = ll;
    }
}

// ---------------- fused causal conv+silu and dt=softplus ----------------
__global__ void conv_dt_kernel(const float* __restrict__ zx, const float* __restrict__ w,
                               const float* __restrict__ bias, const float* __restrict__ dt_bias,
                               float* __restrict__ out, float* __restrict__ dt) {
    int idx = blockIdx.x * blockDim.x + threadIdx.x;
    if (idx < MTOK * CONVDIM) {
        int c = idx % CONVDIM;
        int m = idx / CONVDIM;
        int l = m % SEQ;
        int b = m / SEQ;
        float acc = bias[c];
        #pragma unroll
        for (int k = 0; k < DCONV; k++) {
            int lp = l + k - (DCONV - 1);
            if (lp >= 0)
                acc = fmaf(zx[((size_t)(b * SEQ + lp)) * DINPROJ + DINNER + c], w[c * DCONV + k], acc);
        }
        out[(size_t)m * CONVDIM + c] = siluf(acc);
    } else {
        int k = idx - MTOK * CONVDIM;
        if (k < MTOK * NHEADS) {
            int m = k >> 4;
            int h = k & 15;
            float x = zx[(size_t)m * DINPROJ + (2 * DINNER + 2 * DSTATE) + h] + dt_bias[h];
            dt[k] = (x > 20.0f) ? x : log1pf(expf(x));
        }
    }
}

// ---------------- SSD sequential scan ----------------
__global__ void __launch_bounds__(256) ssd_scan_kernel(
        const float* __restrict__ xbc, const float* __restrict__ dt,
        const float* __restrict__ A_log, const float* __restrict__ Dv,
        float* __restrict__ y)
{
    const int blk  = blockIdx.x;
    const int b    = blk >> 3, pair = blk & 7;
    const int tid  = threadIdx.x;
    const int hsel = tid >> 7;
    const int wg   = tid & 127;
    const int p    = wg >> 1;
    const int nh   = wg & 1;
    const int hh   = pair * 2 + hsel;
    const float A  = -expf(A_log[hh]);
    const float Dh = Dv[hh];

    __shared__ __align__(16) float sBC[6][256];
    __shared__ __align__(16) float sX [6][128];
    __shared__ __align__(16) float sDT[6][16];

    u64t hs2[32];
    #pragma unroll
    for (int i = 0; i < 32; i++) hs2[i] = 0ULL;

    const size_t base = (size_t)b * SEQ;
    const uint32_t bcAddr = smem_u32(&sBC[0][0]);
    const uint32_t xAddr  = smem_u32(&sX[0][0]);
    const uint32_t dtAddr = smem_u32(&sDT[0][0]);

    #define SSD_PF(l) do {                                                        \
        int _buf = (l) % 6;                                                        \
        const float* _row = xbc + (base + (l)) * CONVDIM;                          \
        if (tid < 64)       cp16(bcAddr + _buf * 1024 + tid * 16, _row + DINNER + tid * 4); \
        else if (tid < 96)  cp16(xAddr + _buf * 512 + (tid - 64) * 16, _row + pair * 128 + (tid - 64) * 4); \
        else if (tid < 100) cp16(dtAddr + _buf * 64 + (tid - 96) * 16, dt + (base + (l)) * NHEADS + (tid - 96) * 4); \
    } while (0)

    #define SSD_STEP(l) do {                                                      \
        const int _bf = (l) % 6;                                                   \
        const float dtv = sDT[_bf][hh];                                            \
        const float xp  = sX[_bf][hsel * 64 + p];                                  \
        const float dA  = expf(dtv * A);                                           \
        const float dbx = dtv * xp;                                                \
        const u64t dA2  = pack2(dA, dA);                                           \
        const u64t dbx2 = pack2(dbx, dbx);                                         \
        const u64t* B2 = reinterpret_cast<const u64t*>(&sBC[_bf][nh * 64]);        \
        const u64t* C2 = reinterpret_cast<const u64t*>(&sBC[_bf][128 + nh * 64]);  \
        u64t accA = 0ULL, accB = 0ULL;                                             \
        _Pragma("unroll")                                                          \
        for (int i = 0; i < 16; ++i) {                                             \
            u64t b0 = B2[2*i], b1 = B2[2*i+1];                                     \
            u64t c0 = C2[2*i], c1 = C2[2*i+1];                                     \
            hs2[2*i]   = fma2(dA2, hs2[2*i],   mul2(dbx2, b0));                    \
            accA       = fma2(hs2[2*i],   c0, accA);                               \
            hs2[2*i+1] = fma2(dA2, hs2[2*i+1], mul2(dbx2, b1));                    \
            accB       = fma2(hs2[2*i+1], c1, accB);                               \
        }                                                                          \
        float ax, ay, bx, by;                                                      \
        unpack2(accA, ax, ay);                                                     \
        unpack2(accB, bx, by);                                                     \
        float sum = (ax + ay) + (bx + by);                                         \
        sum += __shfl_xor_sync(0xffffffffu, sum, 1);                               \
        if (nh == 0)                                                               \
            y[(base + (l)) * DINNER + hh * HEADDIM + p] = fmaf(Dh, xp, sum);       \
    } while (0)

    SSD_PF(0); SSD_PF(1);
    asm volatile("cp.async.commit_group;" ::: "memory");
    SSD_PF(2); SSD_PF(3);
    asm volatile("cp.async.commit_group;" ::: "memory");

    for (int l = 0; l < SEQ; l += 2) {
        if (l + 2 < SEQ) asm volatile("cp.async.wait_group 1;" ::: "memory");
        else             asm volatile("cp.async.wait_group 0;" ::: "memory");
        __syncthreads();
        if (l + 4 < SEQ) {
            SSD_PF(l + 4); SSD_PF(l + 5);
            asm volatile("cp.async.commit_group;" ::: "memory");
        }
        SSD_STEP(l);
        SSD_STEP(l + 1);
    }
    #undef SSD_PF
    #undef SSD_STEP
}

// ---------------- gated RMSNorm -> bf16 hi/lo ----------------
__global__ void gate_rms_kernel(const float* __restrict__ zx, const float* __restrict__ y,
                                const float* __restrict__ gw,
                                __nv_bfloat16* __restrict__ oh, __nv_bfloat16* __restrict__ ol) {
    int m = blockIdx.x;
    const float* zr = zx + (size_t)m * DINPROJ;
    const float* yr = y + (size_t)m * DINNER;
    float v[4]; float ss = 0.f;
    #pragma unroll
    for (int j = 0; j < 4; j++) {
        int d = threadIdx.x + j * 256;
        float z = zr[d];
        float g = yr[d] * siluf(z);
        v[j] = g;
        ss += g * g;
    }
    float tot = blockReduceSum(ss);
    float scale = rsqrtf(tot * (1.0f / DINNER) + EPSF);
    #pragma unroll
    for (int j = 0; j < 4; j++) {
        int d = threadIdx.x + j * 256;
        float o = v[j] * scale * gw[d];
        __nv_bfloat16 hh, ll;
        bf16split(o, &hh, &ll);
        oh[(size_t)m * DINNER + d] = hh;
        ol[(size_t)m * DINNER + d] = ll;
    }
}

// ---------------- loss ----------------
__global__ void zero_loss_kernel(float* p) { *p = 0.f; }

__global__ void loss_kernel(const float* __restrict__ logits, const int* __restrict__ targets,
                            float* __restrict__ acc) {
    int gwid = (blockIdx.x * blockDim.x + threadIdx.x) >> 5;
    int lane = threadIdx.x & 31;
    if (gwid >= MTOK) return;
    const float* row = logits + (size_t)gwid * VOCAB;
    float mx = -1e30f;
    #pragma unroll
    for (int i = lane; i < VOCAB; i += 32) mx = fmaxf(mx, row[i]);
    #pragma unroll
    for (int o = 16; o > 0; o >>= 1) mx = fmaxf(mx, __shfl_xor_sync(0xffffffffu, mx, o));
    float s = 0.f;
    #pragma unroll
    for (int i = lane; i < VOCAB; i += 32) s += expf(row[i] - mx);
    #pragma unroll
    for (int o = 16; o > 0; o >>= 1) s += __shfl_xor_sync(0xffffffffu, s, o);
    if (lane == 0) {
        float lse = mx + logf(s);
        atomicAdd(acc, lse - row[targets[gwid]]);
    }
}

__global__ void fin_loss_kernel(const float* sum, float* dst) {
    *dst = (*sum) * (1.0f / (float)MTOK);
}

// ---------------- host launcher ----------------
extern "C" void kernel_launch(void* const* d_in, const int* in_sizes, int n_in,
                              void* d_out, int out_size) {
    const int*   tokens   = (const int*)  d_in[0];
    const int*   targets  = (const int*)  d_in[1];
    const float* emb      = (const float*)d_in[2];
    const float* in_proj  = (const float*)d_in[3];
    const float* conv_w   = (const float*)d_in[4];
    const float* conv_b   = (const float*)d_in[5];
    const float* dt_bias  = (const float*)d_in[6];
    const float* A_log    = (const float*)d_in[7];
    const float* Dv       = (const float*)d_in[8];
    const float* gnorm    = (const float*)d_in[9];
    const float* out_proj = (const float*)d_in[10];
    const float* bnorm    = (const float*)d_in[11];
    const float* fnorm    = (const float*)d_in[12];
    float* out = (float*)d_out;

    float *hid, *res, *zx, *xbc, *dtp, *yb, *lgt, *lsum;
    __nv_bfloat16 *nh, *nl, *gh, *gl, *wih, *wil, *woh, *wol, *eh, *el;
    cudaGetSymbolAddress((void**)&hid,  g_hidden);
    cudaGetSymbolAddress((void**)&res,  g_resid);
    cudaGetSymbolAddress((void**)&zx,   g_zx);
    cudaGetSymbolAddress((void**)&xbc,  g_xbc);
    cudaGetSymbolAddress((void**)&dtp,  g_dt);
    cudaGetSymbolAddress((void**)&yb,   g_y);
    cudaGetSymbolAddress((void**)&lgt,  g_logits);
    cudaGetSymbolAddress((void**)&lsum, g_loss_sum);
    cudaGetSymbolAddress((void**)&nh,   g_nh);
    cudaGetSymbolAddress((void**)&nl,   g_nl);
    cudaGetSymbolAddress((void**)&gh,   g_gh);
    cudaGetSymbolAddress((void**)&gl,   g_gl);
    cudaGetSymbolAddress((void**)&wih,  g_wih);
    cudaGetSymbolAddress((void**)&wil,  g_wil);
    cudaGetSymbolAddress((void**)&woh,  g_woh);
    cudaGetSymbolAddress((void**)&wol,  g_wol);
    cudaGetSymbolAddress((void**)&eh,   g_eh);
    cudaGetSymbolAddress((void**)&el,   g_el);

    cudaFuncSetAttribute(gemm_bf16x3, cudaFuncAttributeMaxDynamicSharedMemorySize, GSMEM);

    {
        long t1 = (long)NLAYER * NINPAD * DMODEL;
        split_pad_kernel<<<(int)((t1 + 255) / 256), 256>>>(in_proj, wih, wil, DINPROJ, NINPAD, DMODEL, t1);
        long t2 = (long)NLAYER * DMODEL * DINNER;
        split_pad_kernel<<<(int)((t2 + 255) / 256), 256>>>(out_proj, woh, wol, DMODEL, DMODEL, DINNER, t2);
        long t3 = (long)VOCAB * DMODEL;
        split_pad_kernel<<<(int)((t3 + 255) / 256), 256>>>(emb, eh, el, VOCAB, VOCAB, DMODEL, t3);
    }

    embed_kernel<<<(MTOK * DMODEL + 255) / 256, 256>>>(tokens, emb, hid, res);

    const int CONV_TOT = MTOK * CONVDIM + MTOK * NHEADS;

    for (int L = 0; L < NLAYER; ++L) {
        add_rms_kernel<<<MTOK, 128>>>(hid, res, bnorm + (size_t)L * DMODEL, nh, nl);

        dim3 g1(NINPAD / 128, MTOK / 128);
        gemm_bf16x3<<<g1, 256, GSMEM>>>(nh, nl,
                                        wih + (size_t)L * NINPAD * DMODEL,
                                        wil + (size_t)L * NINPAD * DMODEL,
                                        zx, MTOK, DINPROJ, DMODEL);

        conv_dt_kernel<<<(CONV_TOT + 255) / 256, 256>>>(
            zx, conv_w + (size_t)L * CONVDIM * DCONV, conv_b + (size_t)L * CONVDIM,
            dt_bias + (size_t)L * NHEADS, xbc, dtp);

        ssd_scan_kernel<<<BATCH * NHEADS / 2, 256>>>(xbc, dtp,
                                                     A_log + (size_t)L * NHEADS,
                                                     Dv + (size_t)L * NHEADS, yb);

        gate_rms_kernel<<<MTOK, 256>>>(zx, yb, gnorm + (size_t)L * DINNER, gh, gl);

        dim3 g2(DMODEL / 128, MTOK / 128);
        gemm_bf16x3<<<g2, 256, GSMEM>>>(gh, gl,
                                        woh + (size_t)L * DMODEL * DINNER,
                                        wol + (size_t)L * DMODEL * DINNER,
                                        hid, MTOK, DMODEL, DINNER);
    }

    add_rms_kernel<<<MTOK, 128>>>(hid, res, fnorm, nh, nl);

    const int LG = MTOK * VOCAB;
    float* logits_dst = (out_size >= LG) ? out : lgt;
    dim3 g3(VOCAB / 128, MTOK / 128);
    gemm_bf16x3<<<g3, 256, GSMEM>>>(nh, nl, eh, el, logits_dst, MTOK, VOCAB, DMODEL);

    zero_loss_kernel<<<1, 1>>>(lsum);
    loss_kernel<<<(MTOK * 32 + 255) / 256, 256>>>(logits_dst, targets, lsum);

    if (out_size > LG)       fin_loss_kernel<<<1, 1>>>(lsum, out + (out_size - 1));
    else if (out_size < LG)  fin_loss_kernel<<<1, 1>>>(lsum, out);
}

// round 9
// speedup vs baseline: 1.0457x; 1.0457x over previous
#include <cuda_runtime.h>
#include <cuda_bf16.h>
#include <math.h>
#include <stdint.h>

// ---------------- problem constants ----------------
#define BATCH   16
#define SEQ     768
#define MTOK    (BATCH*SEQ)       // 12288
#define DMODEL  512
#define DSTATE  128
#define DCONV   4
#define DINNER  1024
#define HEADDIM 64
#define NHEADS  16
#define CONVDIM (DINNER + 2*DSTATE)            // 1280
#define DINPROJ (2*DINNER + 2*DSTATE + NHEADS) // 2320
#define NINPAD  2432                            // 19*128
#define NLAYER  28
#define VOCAB   256
#define EPSF    1e-5f

// ---------------- device scratch ----------------
__device__ float g_hidden[MTOK*DMODEL];
__device__ float g_resid [MTOK*DMODEL];
__device__ float g_zx    [(size_t)MTOK*DINPROJ];
__device__ float g_xbc   [(size_t)MTOK*CONVDIM];
__device__ float g_dt    [MTOK*NHEADS];
__device__ float g_y     [(size_t)MTOK*DINNER];
__device__ float g_logits[(size_t)MTOK*VOCAB];
__device__ float g_loss_sum;

__device__ __nv_bfloat16 g_nh[MTOK*DMODEL],  g_nl[MTOK*DMODEL];
__device__ __nv_bfloat16 g_gh[MTOK*DINNER],  g_gl[MTOK*DINNER];
__device__ __nv_bfloat16 g_wih[(size_t)NLAYER*NINPAD*DMODEL], g_wil[(size_t)NLAYER*NINPAD*DMODEL];
__device__ __nv_bfloat16 g_woh[(size_t)NLAYER*DMODEL*DINNER], g_wol[(size_t)NLAYER*DMODEL*DINNER];
__device__ __nv_bfloat16 g_eh[VOCAB*DMODEL], g_el[VOCAB*DMODEL];

// ---------------- PTX helpers (family-safe) ----------------
__device__ __forceinline__ uint32_t smem_u32(const void* p) {
    uint32_t a;
    asm("{ .reg .u64 t; cvta.to.shared.u64 t, %1; cvt.u32.u64 %0, t; }" : "=r"(a) : "l"(p));
    return a;
}
__device__ __forceinline__ void cp16(uint32_t dst, const void* src) {
    asm volatile("cp.async.cg.shared.global [%0], [%1], 16;" :: "r"(dst), "l"(src));
}
__device__ __forceinline__ void ldm_x4(uint32_t addr, uint32_t& r0, uint32_t& r1, uint32_t& r2, uint32_t& r3) {
    asm volatile("ldmatrix.sync.aligned.m8n8.x4.shared.b16 {%0,%1,%2,%3}, [%4];"
                 : "=r"(r0), "=r"(r1), "=r"(r2), "=r"(r3) : "r"(addr));
}
__device__ __forceinline__ void mma_bf16(float* c, const uint32_t* a, const uint32_t* b) {
    asm volatile(
        "mma.sync.aligned.m16n8k16.row.col.f32.bf16.bf16.f32 "
        "{%0,%1,%2,%3}, {%4,%5,%6,%7}, {%8,%9}, {%0,%1,%2,%3};"
        : "+f"(c[0]), "+f"(c[1]), "+f"(c[2]), "+f"(c[3])
        : "r"(a[0]), "r"(a[1]), "r"(a[2]), "r"(a[3]), "r"(b[0]), "r"(b[1]));
}
typedef unsigned long long u64t;
__device__ __forceinline__ u64t pack2(float x, float y) {
    u64t r; asm("mov.b64 %0, {%1, %2};" : "=l"(r) : "f"(x), "f"(y)); return r;
}
__device__ __forceinline__ u64t mul2(u64t a, u64t b) {
    u64t d; asm("mul.rn.f32x2 %0, %1, %2;" : "=l"(d) : "l"(a), "l"(b)); return d;
}
__device__ __forceinline__ u64t fma2(u64t a, u64t b, u64t c) {
    u64t d; asm("fma.rn.f32x2 %0, %1, %2, %3;" : "=l"(d) : "l"(a), "l"(b), "l"(c)); return d;
}
__device__ __forceinline__ void unpack2(u64t v, float& x, float& y) {
    asm("mov.b64 {%0, %1}, %2;" : "=f"(x), "=f"(y) : "l"(v));
}

// =================================================================
// GEMM A: 128x128 tile, KC=32, 2-stage, 2 CTA/SM (proven R4 config)
// =================================================================
#define ROWB   80
#define SUBT   (128*ROWB)      // 10240 per subtile
#define STAGEB (4*SUBT)        // 40960: Ah, Al, Bh, Bl
#define GSMEM  (2*STAGEB)      // 81920

__device__ __forceinline__ void fill_stage(uint32_t st,
        const __nv_bfloat16* __restrict__ Ah, const __nv_bfloat16* __restrict__ Al,
        const __nv_bfloat16* __restrict__ Bh, const __nv_bfloat16* __restrict__ Bl,
        int bm, int bn, int K, int kc, int tid)
{
    const size_t k0 = (size_t)kc * 32;
    const __nv_bfloat16* srcs[4] = {Ah + (size_t)bm * K + k0, Al + (size_t)bm * K + k0,
                                    Bh + (size_t)bn * K + k0, Bl + (size_t)bn * K + k0};
    #pragma unroll
    for (int s = 0; s < 4; ++s) {
        const __nv_bfloat16* base = srcs[s];
        uint32_t sd = st + s * SUBT;
        #pragma unroll
        for (int i = 0; i < 2; ++i) {
            int lin = tid + (i << 8);
            int row = lin >> 2;
            int ch  = lin & 3;
            cp16(sd + row * ROWB + ch * 16, base + (size_t)row * K + ch * 8);
        }
    }
    asm volatile("cp.async.commit_group;" ::: "memory");
}

__global__ void __launch_bounds__(256, 2) gemm_bf16x3(
    const __nv_bfloat16* __restrict__ Ah, const __nv_bfloat16* __restrict__ Al,
    const __nv_bfloat16* __restrict__ Bh, const __nv_bfloat16* __restrict__ Bl,
    float* __restrict__ C, int M, int N, int K)
{
    extern __shared__ char smem[];
    const uint32_t sb = smem_u32(smem);
    const int tid  = threadIdx.x;
    const int wid  = tid >> 5, lane = tid & 31;
    const int wm   = wid >> 2, wn = wid & 3;
    const int bm   = blockIdx.y * 128, bn = blockIdx.x * 128;

    float acc[4][4][4];
    #pragma unroll
    for (int i = 0; i < 4; i++)
        #pragma unroll
        for (int j = 0; j < 4; j++)
            #pragma unroll
            for (int q = 0; q < 4; q++) acc[i][j][q] = 0.f;

    const int nc = K >> 5;

    fill_stage(sb + 0 * STAGEB, Ah, Al, Bh, Bl, bm, bn, K, 0, tid);
    if (nc > 1) fill_stage(sb + 1 * STAGEB, Ah, Al, Bh, Bl, bm, bn, K, 1, tid);

    const int a_r  = lane & 15;
    const int a_k  = lane >> 4;
    const int b_r  = ((lane >> 4) << 3) + (lane & 7);
    const int b_k  = (lane >> 3) & 1;

    for (int c = 0; c < nc; ++c) {
        const uint32_t st = sb + (uint32_t)(c & 1) * STAGEB;
        if (c + 1 < nc) asm volatile("cp.async.wait_group 1;" ::: "memory");
        else            asm volatile("cp.async.wait_group 0;" ::: "memory");
        __syncthreads();

        const uint32_t a_base = st + (uint32_t)(wm * 64 + a_r) * ROWB + a_k * 16;
        const uint32_t b_base = st + 2 * SUBT + (uint32_t)(wn * 32 + b_r) * ROWB + b_k * 16;

        #pragma unroll
        for (int ks = 0; ks < 2; ++ks) {
            uint32_t bh[4][2], bl[4][2];
            #pragma unroll
            for (int bi = 0; bi < 2; ++bi) {
                uint32_t addr = b_base + (uint32_t)(bi * 16) * ROWB + ks * 32;
                ldm_x4(addr,        bh[2*bi][0], bh[2*bi][1], bh[2*bi+1][0], bh[2*bi+1][1]);
                ldm_x4(addr + SUBT, bl[2*bi][0], bl[2*bi][1], bl[2*bi+1][0], bl[2*bi+1][1]);
            }
            #pragma unroll
            for (int mi = 0; mi < 4; ++mi) {
                uint32_t ah[4], al[4];
                uint32_t addr = a_base + (uint32_t)(mi * 16) * ROWB + ks * 32;
                ldm_x4(addr,        ah[0], ah[1], ah[2], ah[3]);
                ldm_x4(addr + SUBT, al[0], al[1], al[2], al[3]);
                #pragma unroll
                for (int ni = 0; ni < 4; ++ni) mma_bf16(acc[mi][ni], ah, bh[ni]);
                #pragma unroll
                for (int ni = 0; ni < 4; ++ni) mma_bf16(acc[mi][ni], ah, bl[ni]);
                #pragma unroll
                for (int ni = 0; ni < 4; ++ni) mma_bf16(acc[mi][ni], al, bh[ni]);
            }
        }
        __syncthreads();
        int cn = c + 2;
        if (cn < nc)
            fill_stage(st, Ah, Al, Bh, Bl, bm, bn, K, cn, tid);
    }

    const int r  = lane >> 2;
    const int cc = (lane & 3) << 1;
    #pragma unroll
    for (int mi = 0; mi < 4; ++mi) {
        int m0 = bm + wm * 64 + mi * 16 + r;
        #pragma unroll
        for (int ni = 0; ni < 4; ++ni) {
            int n0 = bn + wn * 32 + ni * 8 + cc;
            if (n0 < N) {
                *reinterpret_cast<float2*>(C + (size_t)m0 * N + n0) =
                    make_float2(acc[mi][ni][0], acc[mi][ni][1]);
                *reinterpret_cast<float2*>(C + (size_t)(m0 + 8) * N + n0) =
                    make_float2(acc[mi][ni][2], acc[mi][ni][3]);
            }
        }
    }
}

// =================================================================
// GEMM B (in_proj): 256x128 tile, 64x64 warp tiles, KC=32, 3-stage,
// 1 CTA/SM, prefetch distance 2 — 1.5x less smem fragment traffic.
// =================================================================
#define ASUB2  (256*ROWB)                 // 20480
#define BSUB2  (128*ROWB)                 // 10240
#define STAGE2 (2*ASUB2 + 2*BSUB2)        // 61440
#define GSMEM2 (3*STAGE2)                 // 184320

__device__ __forceinline__ void fill_stage_big(uint32_t st,
        const __nv_bfloat16* __restrict__ Ah, const __nv_bfloat16* __restrict__ Al,
        const __nv_bfloat16* __restrict__ Bh, const __nv_bfloat16* __restrict__ Bl,
        int bm, int bn, int K, int kc, int tid)
{
    const size_t k0 = (size_t)kc * 32;
    const __nv_bfloat16* a0 = Ah + (size_t)bm * K + k0;
    const __nv_bfloat16* a1 = Al + (size_t)bm * K + k0;
    #pragma unroll
    for (int i = 0; i < 4; ++i) {
        int lin = tid + (i << 8);
        int row = lin >> 2, ch = lin & 3;
        uint32_t soff = (uint32_t)row * ROWB + (uint32_t)ch * 16;
        size_t goff = (size_t)row * K + (size_t)ch * 8;
        cp16(st + soff,         a0 + goff);
        cp16(st + ASUB2 + soff, a1 + goff);
    }
    const __nv_bfloat16* b0 = Bh + (size_t)bn * K + k0;
    const __nv_bfloat16* b1 = Bl + (size_t)bn * K + k0;
    #pragma unroll
    for (int i = 0; i < 2; ++i) {
        int lin = tid + (i << 8);
        int row = lin >> 2, ch = lin & 3;
        uint32_t soff = (uint32_t)row * ROWB + (uint32_t)ch * 16;
        size_t goff = (size_t)row * K + (size_t)ch * 8;
        cp16(st + 2 * ASUB2 + soff,         b0 + goff);
        cp16(st + 2 * ASUB2 + BSUB2 + soff, b1 + goff);
    }
    asm volatile("cp.async.commit_group;" ::: "memory");
}

__global__ void __launch_bounds__(256, 1) gemm_bf16x3_big(
    const __nv_bfloat16* __restrict__ Ah, const __nv_bfloat16* __restrict__ Al,
    const __nv_bfloat16* __restrict__ Bh, const __nv_bfloat16* __restrict__ Bl,
    float* __restrict__ C, int M, int N, int K)
{
    extern __shared__ char smem[];
    const uint32_t sb = smem_u32(smem);
    const int tid  = threadIdx.x;
    const int wid  = tid >> 5, lane = tid & 31;
    const int wm   = wid >> 1, wn = wid & 1;    // 4 x 2 warp grid, 64x64 tiles
    const int bm   = blockIdx.y * 256, bn = blockIdx.x * 128;

    float acc[4][8][4];
    #pragma unroll
    for (int i = 0; i < 4; i++)
        #pragma unroll
        for (int j = 0; j < 8; j++)
            #pragma unroll
            for (int q = 0; q < 4; q++) acc[i][j][q] = 0.f;

    const int nc = K >> 5;

    fill_stage_big(sb + 0 * STAGE2, Ah, Al, Bh, Bl, bm, bn, K, 0, tid);
    if (nc > 1) fill_stage_big(sb + 1 * STAGE2, Ah, Al, Bh, Bl, bm, bn, K, 1, tid);

    const int a_r = lane & 15;
    const int a_k = lane >> 4;
    const int b_r = ((lane >> 4) << 3) + (lane & 7);
    const int b_k = (lane >> 3) & 1;

    for (int c = 0; c < nc; ++c) {
        if (c + 1 < nc) asm volatile("cp.async.wait_group 1;" ::: "memory");
        else            asm volatile("cp.async.wait_group 0;" ::: "memory");
        __syncthreads();    // also frees stage (c-1)%3 == (c+2)%3

        if (c + 2 < nc)
            fill_stage_big(sb + (uint32_t)((c + 2) % 3) * STAGE2, Ah, Al, Bh, Bl, bm, bn, K, c + 2, tid);

        const uint32_t st = sb + (uint32_t)(c % 3) * STAGE2;
        const uint32_t a_base = st + (uint32_t)(wm * 64 + a_r) * ROWB + a_k * 16;
        const uint32_t b_base = st + 2 * ASUB2 + (uint32_t)(wn * 64 + b_r) * ROWB + b_k * 16;

        #pragma unroll
        for (int ks = 0; ks < 2; ++ks) {
            uint32_t bh[8][2], bl[8][2];
            #pragma unroll
            for (int bi = 0; bi < 4; ++bi) {
                uint32_t addr = b_base + (uint32_t)(bi * 16) * ROWB + ks * 32;
                ldm_x4(addr,         bh[2*bi][0], bh[2*bi][1], bh[2*bi+1][0], bh[2*bi+1][1]);
                ldm_x4(addr + BSUB2, bl[2*bi][0], bl[2*bi][1], bl[2*bi+1][0], bl[2*bi+1][1]);
            }
            #pragma unroll
            for (int mi = 0; mi < 4; ++mi) {
                uint32_t ah[4], al[4];
                uint32_t addr = a_base + (uint32_t)(mi * 16) * ROWB + ks * 32;
                ldm_x4(addr,         ah[0], ah[1], ah[2], ah[3]);
                ldm_x4(addr + ASUB2, al[0], al[1], al[2], al[3]);
                #pragma unroll
                for (int ni = 0; ni < 8; ++ni) mma_bf16(acc[mi][ni], ah, bh[ni]);
                #pragma unroll
                for (int ni = 0; ni < 8; ++ni) mma_bf16(acc[mi][ni], ah, bl[ni]);
                #pragma unroll
                for (int ni = 0; ni < 8; ++ni) mma_bf16(acc[mi][ni], al, bh[ni]);
            }
        }
    }

    const int r  = lane >> 2;
    const int cc = (lane & 3) << 1;
    #pragma unroll
    for (int mi = 0; mi < 4; ++mi) {
        int m0 = bm + wm * 64 + mi * 16 + r;
        #pragma unroll
        for (int ni = 0; ni < 8; ++ni) {
            int n0 = bn + wn * 64 + ni * 8 + cc;
            if (n0 < N) {
                *reinterpret_cast<float2*>(C + (size_t)m0 * N + n0) =
                    make_float2(acc[mi][ni][0], acc[mi][ni][1]);
                *reinterpret_cast<float2*>(C + (size_t)(m0 + 8) * N + n0) =
                    make_float2(acc[mi][ni][2], acc[mi][ni][3]);
            }
        }
    }
}

// ---------------- generic helpers ----------------
__device__ __forceinline__ float blockReduceSum(float v) {
    __shared__ float sh[32];
    int lane = threadIdx.x & 31, wid = threadIdx.x >> 5;
    #pragma unroll
    for (int o = 16; o > 0; o >>= 1) v += __shfl_xor_sync(0xffffffffu, v, o);
    if (lane == 0) sh[wid] = v;
    __syncthreads();
    if (threadIdx.x == 0) {
        float t = 0.f;
        int nw = (blockDim.x + 31) >> 5;
        for (int i = 0; i < nw; i++) t += sh[i];
        sh[0] = t;
    }
    __syncthreads();
    return sh[0];
}
__device__ __forceinline__ float siluf(float x) { return x / (1.0f + expf(-x)); }

__device__ __forceinline__ void bf16split(float v, __nv_bfloat16* h, __nv_bfloat16* l) {
    __nv_bfloat16 hb = __float2bfloat16(v);
    *h = hb;
    *l = __float2bfloat16(v - __bfloat162float(hb));
}

// ---------------- weight split (with row padding) ----------------
__global__ void split_pad_kernel(const float* __restrict__ src, __nv_bfloat16* __restrict__ h,
                                 __nv_bfloat16* __restrict__ l, int nt, int np, int K, long total) {
    long idx = (long)blockIdx.x * blockDim.x + threadIdx.x;
    if (idx >= total) return;
    int k = (int)(idx % K);
    long t = idx / K;
    int r  = (int)(t % np);
    int ly = (int)(t / np);
    float v = (r < nt) ? src[((size_t)ly * nt + r) * K + k] : 0.0f;
    __nv_bfloat16 hh, ll;
    bf16split(v, &hh, &ll);
    h[idx] = hh; l[idx] = ll;
}

// ---------------- embedding + residual init ----------------
__global__ void embed_kernel(const int* __restrict__ tokens, const float* __restrict__ emb,
                             float* __restrict__ hid, float* __restrict__ res) {
    int idx = blockIdx.x * blockDim.x + threadIdx.x;
    if (idx >= MTOK * DMODEL) return;
    int m = idx >> 9;
    int d = idx & 511;
    hid[idx] = emb[tokens[m] * DMODEL + d];
    res[idx] = 0.0f;
}

// res += h ; out = rms(res)*w -> bf16 hi/lo
__global__ void add_rms_kernel(const float* __restrict__ h, float* __restrict__ res,
                               const float* __restrict__ w,
                               __nv_bfloat16* __restrict__ oh, __nv_bfloat16* __restrict__ ol) {
    int m = blockIdx.x;
    const float* hr = h + (size_t)m * DMODEL;
    float* rr = res + (size_t)m * DMODEL;
    float v[4]; float ss = 0.f;
    #pragma unroll
    for (int j = 0; j < 4; j++) {
        int d = threadIdx.x + j * 128;
        float x = hr[d] + rr[d];
        rr[d] = x;
        v[j] = x;
        ss += x * x;
    }
    float tot = blockReduceSum(ss);
    float scale = rsqrtf(tot * (1.0f / DMODEL) + EPSF);
    #pragma unroll
    for (int j = 0; j < 4; j++) {
        int d = threadIdx.x + j * 128;
        float o = v[j] * scale * w[d];
        __nv_bfloat16 hh, ll;
        bf16split(o, &hh, &ll);
        oh[(size_t)m * DMODEL + d] = hh;
        ol[(size_t)m * DMODEL + d] = ll;
    }
}

// ---------------- fused causal conv+silu and dt=softplus ----------------
__global__ void conv_dt_kernel(const float* __restrict__ zx, const float* __restrict__ w,
                               const float* __restrict__ bias, const float* __restrict__ dt_bias,
                               float* __restrict__ out, float* __restrict__ dt) {
    int idx = blockIdx.x * blockDim.x + threadIdx.x;
    if (idx < MTOK * CONVDIM) {
        int c = idx % CONVDIM;
        int m = idx / CONVDIM;
        int l = m % SEQ;
        int b = m / SEQ;
        float acc = bias[c];
        #pragma unroll
        for (int k = 0; k < DCONV; k++) {
            int lp = l + k - (DCONV - 1);
            if (lp >= 0)
                acc = fmaf(zx[((size_t)(b * SEQ + lp)) * DINPROJ + DINNER + c], w[c * DCONV + k], acc);
        }
        out[(size_t)m * CONVDIM + c] = siluf(acc);
    } else {
        int k = idx - MTOK * CONVDIM;
        if (k < MTOK * NHEADS) {
            int m = k >> 4;
            int h = k & 15;
            float x = zx[(size_t)m * DINPROJ + (2 * DINNER + 2 * DSTATE) + h] + dt_bias[h];
            dt[k] = (x > 20.0f) ? x : log1pf(expf(x));
        }
    }
}

// ---------------- SSD sequential scan ----------------
__global__ void __launch_bounds__(256) ssd_scan_kernel(
        const float* __restrict__ xbc, const float* __restrict__ dt,
        const float* __restrict__ A_log, const float* __restrict__ Dv,
        float* __restrict__ y)
{
    const int blk  = blockIdx.x;
    const int b    = blk >> 3, pair = blk & 7;
    const int tid  = threadIdx.x;
    const int hsel = tid >> 7;
    const int wg   = tid & 127;
    const int p    = wg >> 1;
    const int nh   = wg & 1;
    const int hh   = pair * 2 + hsel;
    const float A  = -expf(A_log[hh]);
    const float Dh = Dv[hh];

    __shared__ __align__(16) float sBC[6][256];
    __shared__ __align__(16) float sX [6][128];
    __shared__ __align__(16) float sDT[6][16];

    u64t hs2[32];
    #pragma unroll
    for (int i = 0; i < 32; i++) hs2[i] = 0ULL;

    const size_t base = (size_t)b * SEQ;
    const uint32_t bcAddr = smem_u32(&sBC[0][0]);
    const uint32_t xAddr  = smem_u32(&sX[0][0]);
    const uint32_t dtAddr = smem_u32(&sDT[0][0]);

    #define SSD_PF(l) do {                                                        \
        int _buf = (l) % 6;                                                        \
        const float* _row = xbc + (base + (l)) * CONVDIM;                          \
        if (tid < 64)       cp16(bcAddr + _buf * 1024 + tid * 16, _row + DINNER + tid * 4); \
        else if (tid < 96)  cp16(xAddr + _buf * 512 + (tid - 64) * 16, _row + pair * 128 + (tid - 64) * 4); \
        else if (tid < 100) cp16(dtAddr + _buf * 64 + (tid - 96) * 16, dt + (base + (l)) * NHEADS + (tid - 96) * 4); \
    } while (0)

    #define SSD_STEP(l) do {                                                      \
        const int _bf = (l) % 6;                                                   \
        const float dtv = sDT[_bf][hh];                                            \
        const float xp  = sX[_bf][hsel * 64 + p];                                  \
        const float dA  = expf(dtv * A);                                           \
        const float dbx = dtv * xp;                                                \
        const u64t dA2  = pack2(dA, dA);                                           \
        const u64t dbx2 = pack2(dbx, dbx);                                         \
        const u64t* B2 = reinterpret_cast<const u64t*>(&sBC[_bf][nh * 64]);        \
        const u64t* C2 = reinterpret_cast<const u64t*>(&sBC[_bf][128 + nh * 64]);  \
        u64t accA = 0ULL, accB = 0ULL;                                             \
        _Pragma("unroll")                                                          \
        for (int i = 0; i < 16; ++i) {                                             \
            u64t b0 = B2[2*i], b1 = B2[2*i+1];                                     \
            u64t c0 = C2[2*i], c1 = C2[2*i+1];                                     \
            hs2[2*i]   = fma2(dA2, hs2[2*i],   mul2(dbx2, b0));                    \
            accA       = fma2(hs2[2*i],   c0, accA);                               \
            hs2[2*i+1] = fma2(dA2, hs2[2*i+1], mul2(dbx2, b1));                    \
            accB       = fma2(hs2[2*i+1], c1, accB);                               \
        }                                                                          \
        float ax, ay, bx, by;                                                      \
        unpack2(accA, ax, ay);                                                     \
        unpack2(accB, bx, by);                                                     \
        float sum = (ax + ay) + (bx + by);                                         \
        sum += __shfl_xor_sync(0xffffffffu, sum, 1);                               \
        if (nh == 0)                                                               \
            y[(base + (l)) * DINNER + hh * HEADDIM + p] = fmaf(Dh, xp, sum);       \
    } while (0)

    SSD_PF(0); SSD_PF(1);
    asm volatile("cp.async.commit_group;" ::: "memory");
    SSD_PF(2); SSD_PF(3);
    asm volatile("cp.async.commit_group;" ::: "memory");

    for (int l = 0; l < SEQ; l += 2) {
        if (l + 2 < SEQ) asm volatile("cp.async.wait_group 1;" ::: "memory");
        else             asm volatile("cp.async.wait_group 0;" ::: "memory");
        __syncthreads();
        if (l + 4 < SEQ) {
            SSD_PF(l + 4); SSD_PF(l + 5);
            asm volatile("cp.async.commit_group;" ::: "memory");
        }
        SSD_STEP(l);
        SSD_STEP(l + 1);
    }
    #undef SSD_PF
    #undef SSD_STEP
}

// ---------------- gated RMSNorm -> bf16 hi/lo ----------------
__global__ void gate_rms_kernel(const float* __restrict__ zx, const float* __restrict__ y,
                                const float* __restrict__ gw,
                                __nv_bfloat16* __restrict__ oh, __nv_bfloat16* __restrict__ ol) {
    int m = blockIdx.x;
    const float* zr = zx + (size_t)m * DINPROJ;
    const float* yr = y + (size_t)m * DINNER;
    float v[4]; float ss = 0.f;
    #pragma unroll
    for (int j = 0; j < 4; j++) {
        int d = threadIdx.x + j * 256;
        float z = zr[d];
        float g = yr[d] * siluf(z);
        v[j] = g;
        ss += g * g;
    }
    float tot = blockReduceSum(ss);
    float scale = rsqrtf(tot * (1.0f / DINNER) + EPSF);
    #pragma unroll
    for (int j = 0; j < 4; j++) {
        int d = threadIdx.x + j * 256;
        float o = v[j] * scale * gw[d];
        __nv_bfloat16 hh, ll;
        bf16split(o, &hh, &ll);
        oh[(size_t)m * DINNER + d] = hh;
        ol[(size_t)m * DINNER + d] = ll;
    }
}

// ---------------- loss ----------------
__global__ void zero_loss_kernel(float* p) { *p = 0.f; }

__global__ void loss_kernel(const float* __restrict__ logits, const int* __restrict__ targets,
                            float* __restrict__ acc) {
    int gwid = (blockIdx.x * blockDim.x + threadIdx.x) >> 5;
    int lane = threadIdx.x & 31;
    if (gwid >= MTOK) return;
    const float* row = logits + (size_t)gwid * VOCAB;
    float mx = -1e30f;
    #pragma unroll
    for (int i = lane; i < VOCAB; i += 32) mx = fmaxf(mx, row[i]);
    #pragma unroll
    for (int o = 16; o > 0; o >>= 1) mx = fmaxf(mx, __shfl_xor_sync(0xffffffffu, mx, o));
    float s = 0.f;
    #pragma unroll
    for (int i = lane; i < VOCAB; i += 32) s += expf(row[i] - mx);
    #pragma unroll
    for (int o = 16; o > 0; o >>= 1) s += __shfl_xor_sync(0xffffffffu, s, o);
    if (lane == 0) {
        float lse = mx + logf(s);
        atomicAdd(acc, lse - row[targets[gwid]]);
    }
}

__global__ void fin_loss_kernel(const float* sum, float* dst) {
    *dst = (*sum) * (1.0f / (float)MTOK);
}

// ---------------- host launcher ----------------
extern "C" void kernel_launch(void* const* d_in, const int* in_sizes, int n_in,
                              void* d_out, int out_size) {
    const int*   tokens   = (const int*)  d_in[0];
    const int*   targets  = (const int*)  d_in[1];
    const float* emb      = (const float*)d_in[2];
    const float* in_proj  = (const float*)d_in[3];
    const float* conv_w   = (const float*)d_in[4];
    const float* conv_b   = (const float*)d_in[5];
    const float* dt_bias  = (const float*)d_in[6];
    const float* A_log    = (const float*)d_in[7];
    const float* Dv       = (const float*)d_in[8];
    const float* gnorm    = (const float*)d_in[9];
    const float* out_proj = (const float*)d_in[10];
    const float* bnorm    = (const float*)d_in[11];
    const float* fnorm    = (const float*)d_in[12];
    float* out = (float*)d_out;

    float *hid, *res, *zx, *xbc, *dtp, *yb, *lgt, *lsum;
    __nv_bfloat16 *nh, *nl, *gh, *gl, *wih, *wil, *woh, *wol, *eh, *el;
    cudaGetSymbolAddress((void**)&hid,  g_hidden);
    cudaGetSymbolAddress((void**)&res,  g_resid);
    cudaGetSymbolAddress((void**)&zx,   g_zx);
    cudaGetSymbolAddress((void**)&xbc,  g_xbc);
    cudaGetSymbolAddress((void**)&dtp,  g_dt);
    cudaGetSymbolAddress((void**)&yb,   g_y);
    cudaGetSymbolAddress((void**)&lgt,  g_logits);
    cudaGetSymbolAddress((void**)&lsum, g_loss_sum);
    cudaGetSymbolAddress((void**)&nh,   g_nh);
    cudaGetSymbolAddress((void**)&nl,   g_nl);
    cudaGetSymbolAddress((void**)&gh,   g_gh);
    cudaGetSymbolAddress((void**)&gl,   g_gl);
    cudaGetSymbolAddress((void**)&wih,  g_wih);
    cudaGetSymbolAddress((void**)&wil,  g_wil);
    cudaGetSymbolAddress((void**)&woh,  g_woh);
    cudaGetSymbolAddress((void**)&wol,  g_wol);
    cudaGetSymbolAddress((void**)&eh,   g_eh);
    cudaGetSymbolAddress((void**)&el,   g_el);

    cudaFuncSetAttribute(gemm_bf16x3,     cudaFuncAttributeMaxDynamicSharedMemorySize, GSMEM);
    cudaFuncSetAttribute(gemm_bf16x3_big, cudaFuncAttributeMaxDynamicSharedMemorySize, GSMEM2);

    {
        long t1 = (long)NLAYER * NINPAD * DMODEL;
        split_pad_kernel<<<(int)((t1 + 255) / 256), 256>>>(in_proj, wih, wil, DINPROJ, NINPAD, DMODEL, t1);
        long t2 = (long)NLAYER * DMODEL * DINNER;
        split_pad_kernel<<<(int)((t2 + 255) / 256), 256>>>(out_proj, woh, wol, DMODEL, DMODEL, DINNER, t2);
        long t3 = (long)VOCAB * DMODEL;
        split_pad_kernel<<<(int)((t3 + 255) / 256), 256>>>(emb, eh, el, VOCAB, VOCAB, DMODEL, t3);
    }

    embed_kernel<<<(MTOK * DMODEL + 255) / 256, 256>>>(tokens, emb, hid, res);

    const int CONV_TOT = MTOK * CONVDIM + MTOK * NHEADS;

    for (int L = 0; L < NLAYER; ++L) {
        add_rms_kernel<<<MTOK, 128>>>(hid, res, bnorm + (size_t)L * DMODEL, nh, nl);

        dim3 g1(NINPAD / 128, MTOK / 256);
        gemm_bf16x3_big<<<g1, 256, GSMEM2>>>(nh, nl,
                                             wih + (size_t)L * NINPAD * DMODEL,
                                             wil + (size_t)L * NINPAD * DMODEL,
                                             zx, MTOK, DINPROJ, DMODEL);

        conv_dt_kernel<<<(CONV_TOT + 255) / 256, 256>>>(
            zx, conv_w + (size_t)L * CONVDIM * DCONV, conv_b + (size_t)L * CONVDIM,
            dt_bias + (size_t)L * NHEADS, xbc, dtp);

        ssd_scan_kernel<<<BATCH * NHEADS / 2, 256>>>(xbc, dtp,
                                                     A_log + (size_t)L * NHEADS,
                                                     Dv + (size_t)L * NHEADS, yb);

        gate_rms_kernel<<<MTOK, 256>>>(zx, yb, gnorm + (size_t)L * DINNER, gh, gl);

        dim3 g2(DMODEL / 128, MTOK / 128);
        gemm_bf16x3<<<g2, 256, GSMEM>>>(gh, gl,
                                        woh + (size_t)L * DMODEL * DINNER,
                                        wol + (size_t)L * DMODEL * DINNER,
                                        hid, MTOK, DMODEL, DINNER);
    }

    add_rms_kernel<<<MTOK, 128>>>(hid, res, fnorm, nh, nl);

    const int LG = MTOK * VOCAB;
    float* logits_dst = (out_size >= LG) ? out : lgt;
    dim3 g3(VOCAB / 128, MTOK / 128);
    gemm_bf16x3<<<g3, 256, GSMEM>>>(nh, nl, eh, el, logits_dst, MTOK, VOCAB, DMODEL);

    zero_loss_kernel<<<1, 1>>>(lsum);
    loss_kernel<<<(MTOK * 32 + 255) / 256, 256>>>(logits_dst, targets, lsum);

    if (out_size > LG)       fin_loss_kernel<<<1, 1>>>(lsum, out + (out_size - 1));
    else if (out_size < LG)  fin_loss_kernel<<<1, 1>>>(lsum, out);
}